// round 9
// baseline (speedup 1.0000x reference)
#include <cuda_runtime.h>
#include <cuda_bf16.h>
#include <cstdint>

typedef unsigned long long ull;

// ---------------- problem constants ----------------
#define BSZ 2
#define SEQ 2048
#define HID 2048
#define HD  256
#define NH  8
#define SCALING 0.0625f

// ---------------- scratch (device globals) ----------------
__device__ float g_Qp [(long)BSZ*SEQ*NH*HD];   // pre-RoPE Q (b,s,h,d)
__device__ float g_Q  [(long)BSZ*NH*SEQ*HD];   // RoPE'd, scaled Q (b,h,s,d)
__device__ float g_KV [(long)BSZ*SEQ*512];     // [token][0:256]=K, [256:512]=V
__device__ float g_Kt [(long)BSZ*HD*SEQ];      // K^T per batch (d, s2)
__device__ float g_AO [(long)BSZ*SEQ*NH*HD];   // attn out (b,s,h*d)
__device__ float g_Wkv[(long)HID*512];         // [Wk | Wv]

// ---------------- helpers ----------------
__device__ __forceinline__ uint32_t smem_u32(const void* p) {
    uint32_t a;
    asm("{ .reg .u64 t; cvta.to.shared.u64 t, %1; cvt.u32.u64 %0, t; }" : "=r"(a) : "l"(p));
    return a;
}
__device__ __forceinline__ void cp_async16(uint32_t dst, const void* src) {
    asm volatile("cp.async.cg.shared.global [%0], [%1], 16;" :: "r"(dst), "l"(src));
}
__device__ __forceinline__ void cp_commit() { asm volatile("cp.async.commit_group;"); }
template<int N> __device__ __forceinline__ void cp_wait() {
    asm volatile("cp.async.wait_group %0;" :: "n"(N));
}
__device__ __forceinline__ ull pk2(float x) {
    ull r; unsigned u = __float_as_uint(x);
    asm("mov.b64 %0, {%1, %1};" : "=l"(r) : "r"(u));
    return r;
}
__device__ __forceinline__ ull fma2(ull a, ull b, ull c) {
    ull d;
    asm("fma.rn.f32x2 %0, %1, %2, %3;" : "=l"(d) : "l"(a), "l"(b), "l"(c));
    return d;
}
__device__ __forceinline__ float2 unpk2(ull v) {
    unsigned lo, hi;
    asm("mov.b64 {%0, %1}, %2;" : "=r"(lo), "=r"(hi) : "l"(v));
    return make_float2(__uint_as_float(lo), __uint_as_float(hi));
}

// ---------------- fp32 GEMM: 128x128 tile, 512 threads, 8x4 microtile -------
// BK=16, 3-stage cp.async, single __syncthreads per chunk.
// C = A(M x K) * B(K x N); row-major. batched via gridDim.z (b=z/nh, h=z%nh).
// causalQK: skip tiles colT > rowT ; causalPV: truncate K at (rowT+1)*128
// stage: A [128][16] (8 KB) + B [16][128] (8 KB) = 16 KB
#define STG_FLOATS 4096
#define NSTG 3
#define SMEM_DYN (NSTG * STG_FLOATS * 4)

__global__ __launch_bounds__(512)
void sgemm2(const float* __restrict__ A, const float* __restrict__ B,
            float* __restrict__ C,
            int K, int lda, int ldb, int ldc,
            long sAz, long sBb, long sCb, long sCh, int nh,
            int causalQK, int causalPV)
{
    extern __shared__ float sm[];
    const int tid = threadIdx.x;
    const int z = blockIdx.z, b = z / nh, h = z - b * nh;
    const int rowT = blockIdx.y, colT = blockIdx.x;
    if (causalQK && colT > rowT) return;

    A += (long)z * sAz + (long)(rowT * 128) * lda;
    B += (long)b * sBb + colT * 128;
    C += (long)b * sCb + (long)h * sCh;

    const int Keff = causalPV ? min(K, (rowT + 1) * 128) : K;
    const int nk = Keff >> 4;

    const uint32_t smb = smem_u32(sm);
    const int tr = tid >> 5;       // 0..15 -> m base tr*8
    const int tc = tid & 31;       // 0..31 -> n base tc*4

    // cp.async ids (one A seg + one B seg per thread)
    const int arow = tid >> 2, aseg = (tid & 3) << 2;   // A: [arow][aseg..aseg+3]
    const int bk   = tid >> 5, bn   = (tid & 31) << 2;  // B: [bk][bn..bn+3]

    ull acc[8][2];
    #pragma unroll
    for (int m = 0; m < 8; m++) { acc[m][0] = 0ull; acc[m][1] = 0ull; }

    #define ISSUE(st, c) do {                                                  \
        uint32_t sa_ = smb + (st) * (STG_FLOATS * 4);                           \
        uint32_t sb_ = sa_ + 8192;                                              \
        cp_async16(sa_ + (arow * 16 + aseg) * 4,                                \
                   A + (long)arow * lda + (c) * 16 + aseg);                     \
        cp_async16(sb_ + (bk * 128 + bn) * 4,                                   \
                   B + (long)((c) * 16 + bk) * ldb + bn);                       \
    } while (0)

    ISSUE(0, 0); cp_commit();
    if (nk > 1) ISSUE(1, 1);
    cp_commit();

    int stg = 0;
    for (int i = 0; i < nk; i++) {
        cp_wait<1>();
        __syncthreads();

        const int nc = i + 2;
        const int nst = (stg + 2 >= NSTG) ? (stg + 2 - NSTG) : (stg + 2);
        if (nc < nk) ISSUE(nst, nc);
        cp_commit();

        const float* sa = sm + stg * STG_FLOATS;       // [m][16]
        const float* sb = sa + 2048;                   // [k][128]

        #pragma unroll
        for (int k2 = 0; k2 < 8; k2++) {
            float2 a2[8];
            #pragma unroll
            for (int j = 0; j < 8; j++)
                a2[j] = *(const float2*)(sa + (tr * 8 + j) * 16 + k2 * 2);
            #pragma unroll
            for (int kk = 0; kk < 2; kk++) {
                const int k = k2 * 2 + kk;
                ulonglong2 bv = *(const ulonglong2*)(sb + k * 128 + tc * 4);
                #pragma unroll
                for (int j = 0; j < 8; j++) {
                    const ull am = pk2(kk ? a2[j].y : a2[j].x);
                    acc[j][0] = fma2(am, bv.x, acc[j][0]);
                    acc[j][1] = fma2(am, bv.y, acc[j][1]);
                }
            }
        }
        stg = (stg + 1 == NSTG) ? 0 : stg + 1;
    }
    #undef ISSUE

    // epilogue: one float4 store per m-row
    #pragma unroll
    for (int j = 0; j < 8; j++) {
        const int r = rowT * 128 + tr * 8 + j;
        float2 v0 = unpk2(acc[j][0]);
        float2 v1 = unpk2(acc[j][1]);
        float4 v = make_float4(v0.x, v0.y, v1.x, v1.y);
        *(float4*)(C + (long)r * ldc + colT * 128 + tc * 4) = v;
    }
}

// ---------------- weight concat [Wk | Wv] ----------------
__global__ void concat_wkv(const float* __restrict__ Wk, const float* __restrict__ Wv,
                           float* __restrict__ Wkv) {
    int idx = blockIdx.x * 256 + threadIdx.x;      // HID*512
    int k = idx >> 9, n = idx & 511;
    Wkv[idx] = (n < 256) ? Wk[k * 256 + n] : Wv[k * 256 + (n - 256)];
}

// ---------------- RoPE Q: block per token ----------------
__global__ __launch_bounds__(256)
void rope_q(const float* __restrict__ Qp, const float* __restrict__ cosb,
            const float* __restrict__ sinb, float* __restrict__ Qt) {
    const int bs = blockIdx.x;            // 0..4095
    const int b = bs >> 11, s = bs & 2047;
    const int d = threadIdx.x;            // 0..255
    const int dp = (d < 128) ? d + 128 : d - 128;
    const float cd = cosb[(long)bs * 256 + d];
    const float sd = sinb[(long)bs * 256 + d];
    const float sgn = (d < 128) ? -1.0f : 1.0f;

    const float* src = Qp + (long)bs * 2048;
    float x[8], xp[8];
    #pragma unroll
    for (int h = 0; h < 8; h++) x[h]  = src[h * 256 + d];
    #pragma unroll
    for (int h = 0; h < 8; h++) xp[h] = src[h * 256 + dp];
    #pragma unroll
    for (int h = 0; h < 8; h++) {
        Qt[(((long)(b * 8 + h) * 2048 + s) << 8) + d] =
            (x[h] * cd + sgn * xp[h] * sd) * SCALING;
    }
}

// ---------------- RoPE K + transpose -> Kt (b, d, s2) ----------------
__global__ void rope_kT(const float* __restrict__ KV, const float* __restrict__ cosb,
                        const float* __restrict__ sinb, float* __restrict__ Kt) {
    __shared__ float t[32][33];
    const int b = blockIdx.z;
    const int d0 = blockIdx.y * 32;
    const int s0 = blockIdx.x * 32;
    const int tx = threadIdx.x, ty = threadIdx.y;

    const int d = d0 + tx;
    const int s2 = s0 + ty;
    const int dp = (d < 128) ? d + 128 : d - 128;
    const long tok = (long)(b * SEQ + s2);
    const float x  = KV[tok * 512 + d];
    const float xp = KV[tok * 512 + dp];
    const float rot = (d < 128) ? -xp : xp;
    const float c = cosb[tok * 256 + d];
    const float sv = sinb[tok * 256 + d];
    t[ty][tx] = x * c + rot * sv;
    __syncthreads();

    Kt[((long)(b * HD + d0 + ty)) * SEQ + s0 + tx] = t[tx][ty];
}

// ---------------- causal softmax ----------------
__global__ __launch_bounds__(256)
void softmax_causal(float* __restrict__ W) {
    const long row = blockIdx.x;                 // (b,h,s1) flat
    const int r = (int)(row & 2047);
    const int len = r + 1;
    float* p = W + row * (long)SEQ;
    const int tid = threadIdx.x;
    __shared__ float red[256];

    float v[8];
    float m = -3.0e38f;
    #pragma unroll
    for (int j = 0; j < 8; j++) {
        const int c = tid + j * 256;
        v[j] = (c < len) ? p[c] : -3.0e38f;
        m = fmaxf(m, v[j]);
    }
    red[tid] = m; __syncthreads();
    for (int s = 128; s > 0; s >>= 1) {
        if (tid < s) red[tid] = fmaxf(red[tid], red[tid + s]);
        __syncthreads();
    }
    m = red[0]; __syncthreads();

    float sum = 0.0f;
    #pragma unroll
    for (int j = 0; j < 8; j++) {
        const int c = tid + j * 256;
        v[j] = (c < len) ? __expf(v[j] - m) : 0.0f;
        sum += v[j];
    }
    red[tid] = sum; __syncthreads();
    for (int s = 128; s > 0; s >>= 1) {
        if (tid < s) red[tid] += red[tid + s];
        __syncthreads();
    }
    const float inv = 1.0f / red[0]; __syncthreads();

    #pragma unroll
    for (int j = 0; j < 8; j++) {
        const int c = tid + j * 256;
        p[c] = v[j] * inv;          // exact 0 above diagonal
    }
}

// ---------------- launch ----------------
extern "C" void kernel_launch(void* const* d_in, const int* in_sizes, int n_in,
                              void* d_out, int out_size)
{
    const float* hs   = (const float*)d_in[0];
    const float* cosb = (const float*)d_in[1];
    const float* sinb = (const float*)d_in[2];
    const float* Wq   = (const float*)d_in[4];
    const float* Wk   = (const float*)d_in[5];
    const float* Wv   = (const float*)d_in[6];
    const float* Wo   = (const float*)d_in[7];

    float* out_attn = (float*)d_out;                          // (B,S,H)
    float* out_w    = (float*)d_out + (long)BSZ * SEQ * HID;  // (B,NH,S,S)

    const long SS = (long)SEQ * SEQ;

    cudaFuncSetAttribute(sgemm2, cudaFuncAttributeMaxDynamicSharedMemorySize, SMEM_DYN);

    // 0) concat K/V weights
    concat_wkv<<<(HID * 512) / 256, 256>>>(Wk, Wv, g_Wkv);

    // 1) Q projection
    sgemm2<<<dim3(16, 32, 1), 512, SMEM_DYN>>>(hs, Wq, g_Qp,
        HID, HID, HID, HID, 0, 0, 0, 0, 1, 0, 0);

    // 2) KV projection
    sgemm2<<<dim3(4, 32, 1), 512, SMEM_DYN>>>(hs, g_Wkv, g_KV,
        HID, HID, 512, 512, 0, 0, 0, 0, 1, 0, 0);

    // 3) RoPE
    rope_q <<<4096, 256>>>(g_Qp, cosb, sinb, g_Q);
    rope_kT<<<dim3(64, 8, 2), dim3(32, 32)>>>(g_KV, cosb, sinb, g_Kt);

    // 4) logits = Q K^T (scaled via Q), causal tile skip
    sgemm2<<<dim3(16, 16, 16), 512, SMEM_DYN>>>(g_Q, g_Kt, out_w,
        HD, HD, SEQ, SEQ,
        (long)SEQ * HD, (long)HD * SEQ, (long)NH * SS, SS, NH, 1, 0);

    // 5) causal softmax
    softmax_causal<<<32768, 256>>>(out_w);

    // 6) attn = P @ V, K-loop truncated by causality
    sgemm2<<<dim3(2, 16, 16), 512, SMEM_DYN>>>(out_w, g_KV + 256, g_AO,
        SEQ, SEQ, 512, HID,
        SS, (long)SEQ * 512, (long)SEQ * HID, (long)HD, NH, 0, 1);

    // 7) output projection
    sgemm2<<<dim3(16, 32, 1), 512, SMEM_DYN>>>(g_AO, Wo, out_attn,
        HID, HID, HID, HID, 0, 0, 0, 0, 1, 0, 0);
}

// round 10
// speedup vs baseline: 2.1279x; 2.1279x over previous
#include <cuda_runtime.h>
#include <cuda_bf16.h>
#include <cstdint>

typedef unsigned long long ull;

// ---------------- problem constants ----------------
#define BSZ 2
#define SEQ 2048
#define HID 2048
#define HD  256
#define NH  8
#define SCALING 0.0625f

// ---------------- scratch (device globals) ----------------
__device__ float g_Qp [(long)BSZ*SEQ*NH*HD];   // pre-RoPE Q (b,s,h,d)
__device__ float g_Q  [(long)BSZ*NH*SEQ*HD];   // RoPE'd, scaled Q (b,h,s,d)
__device__ float g_KV [(long)BSZ*SEQ*512];     // [token][0:256]=K, [256:512]=V
__device__ float g_Kt [(long)BSZ*HD*SEQ];      // K^T per batch (d, s2)
__device__ float g_AO [(long)BSZ*SEQ*NH*HD];   // attn out (b,s,h*d)
__device__ float g_Wkv[(long)HID*512];         // [Wk | Wv]

// ---------------- f32x2 helpers ----------------
__device__ __forceinline__ ull pk2(float x) {
    ull r; unsigned u = __float_as_uint(x);
    asm("mov.b64 %0, {%1, %1};" : "=l"(r) : "r"(u));
    return r;
}
__device__ __forceinline__ ull fma2(ull a, ull b, ull c) {
    ull d;
    asm("fma.rn.f32x2 %0, %1, %2, %3;" : "=l"(d) : "l"(a), "l"(b), "l"(c));
    return d;
}
__device__ __forceinline__ float2 unpk2(ull v) {
    unsigned lo, hi;
    asm("mov.b64 {%0, %1}, %2;" : "=r"(lo), "=r"(hi) : "l"(v));
    return make_float2(__uint_as_float(lo), __uint_as_float(hi));
}

// ---------------- fp32 GEMM: 128x128 tile, 512 threads, 8m x 4n microtile ---
// f32x2 packed along M (A operands load ready-packed from k-major smem).
// BK=16, register-prefetch + STS double buffer (NO cp.async — proven slow).
// C = A(M x K) * B(K x N); row-major. batched via gridDim.z (b=z/nh, h=z%nh).
// causalQK: skip tiles colT > rowT ; causalPV: truncate K at (rowT+1)*128
__global__ __launch_bounds__(512)
void sgemm3(const float* __restrict__ A, const float* __restrict__ B,
            float* __restrict__ C,
            int K, int lda, int ldb, int ldc,
            long sAz, long sBb, long sCb, long sCh, int nh,
            int causalQK, int causalPV)
{
    __shared__ float As[2][16][128];   // [k][m]
    __shared__ float Bs[2][16][128];   // [k][n]

    const int tid = threadIdx.x;
    const int z = blockIdx.z, b = z / nh, h = z - b * nh;
    const int rowT = blockIdx.y, colT = blockIdx.x;
    if (causalQK && colT > rowT) return;

    A += (long)z * sAz + (long)(rowT * 128) * lda;
    B += (long)b * sBb + colT * 128;
    C += (long)b * sCb + (long)h * sCh;

    const int Keff = causalPV ? min(K, (rowT + 1) * 128) : K;
    const int nk = Keff >> 4;

    const int w    = tid >> 5;          // 0..15
    const int lane = tid & 31;
    const int mbase = w * 8;            // 8 m-rows per warp-thread group
    const int nbase = lane * 4;         // 4 n-cols per thread

    // loader indices (1 float4 of A + 1 float4 of B per thread per chunk)
    const int am = tid >> 2, ak = (tid & 3) << 2;     // A[am][ak..ak+3]
    const int bk = tid >> 5, bn = (tid & 31) << 2;    // B[bk][bn..bn+3]

    // stage 0
    float4 pa = *(const float4*)(A + (long)am * lda + ak);
    float4 pb = *(const float4*)(B + (long)bk * ldb + bn);
    As[0][ak + 0][am] = pa.x; As[0][ak + 1][am] = pa.y;
    As[0][ak + 2][am] = pa.z; As[0][ak + 3][am] = pa.w;
    *(float4*)&Bs[0][bk][bn] = pb;
    __syncthreads();

    ull acc[4][4];
    #pragma unroll
    for (int mp = 0; mp < 4; mp++)
        #pragma unroll
        for (int n = 0; n < 4; n++) acc[mp][n] = 0ull;

    for (int s = 0; s < nk; s++) {
        const int buf = s & 1;
        if (s + 1 < nk) {
            pa = *(const float4*)(A + (long)am * lda + (s + 1) * 16 + ak);
            pb = *(const float4*)(B + (long)((s + 1) * 16 + bk) * ldb + bn);
        }
        #pragma unroll
        for (int k = 0; k < 16; k++) {
            ulonglong2 aa0 = *(const ulonglong2*)&As[buf][k][mbase];      // (m0,m1),(m2,m3)
            ulonglong2 aa1 = *(const ulonglong2*)&As[buf][k][mbase + 4];  // (m4,m5),(m6,m7)
            float4 bv = *(const float4*)&Bs[buf][k][nbase];
            const ull b0 = pk2(bv.x), b1 = pk2(bv.y), b2 = pk2(bv.z), b3 = pk2(bv.w);
            acc[0][0] = fma2(aa0.x, b0, acc[0][0]);
            acc[0][1] = fma2(aa0.x, b1, acc[0][1]);
            acc[0][2] = fma2(aa0.x, b2, acc[0][2]);
            acc[0][3] = fma2(aa0.x, b3, acc[0][3]);
            acc[1][0] = fma2(aa0.y, b0, acc[1][0]);
            acc[1][1] = fma2(aa0.y, b1, acc[1][1]);
            acc[1][2] = fma2(aa0.y, b2, acc[1][2]);
            acc[1][3] = fma2(aa0.y, b3, acc[1][3]);
            acc[2][0] = fma2(aa1.x, b0, acc[2][0]);
            acc[2][1] = fma2(aa1.x, b1, acc[2][1]);
            acc[2][2] = fma2(aa1.x, b2, acc[2][2]);
            acc[2][3] = fma2(aa1.x, b3, acc[2][3]);
            acc[3][0] = fma2(aa1.y, b0, acc[3][0]);
            acc[3][1] = fma2(aa1.y, b1, acc[3][1]);
            acc[3][2] = fma2(aa1.y, b2, acc[3][2]);
            acc[3][3] = fma2(aa1.y, b3, acc[3][3]);
        }
        if (s + 1 < nk) {
            __syncthreads();
            const int nb = buf ^ 1;
            As[nb][ak + 0][am] = pa.x; As[nb][ak + 1][am] = pa.y;
            As[nb][ak + 2][am] = pa.z; As[nb][ak + 3][am] = pa.w;
            *(float4*)&Bs[nb][bk][bn] = pb;
            __syncthreads();
        }
    }

    // epilogue: acc[mp] holds rows (mbase+2mp, mbase+2mp+1) x cols nbase..+3
    #pragma unroll
    for (int mp = 0; mp < 4; mp++) {
        float2 u0 = unpk2(acc[mp][0]);
        float2 u1 = unpk2(acc[mp][1]);
        float2 u2 = unpk2(acc[mp][2]);
        float2 u3 = unpk2(acc[mp][3]);
        const int r0 = rowT * 128 + mbase + 2 * mp;
        float* cp = C + (long)r0 * ldc + colT * 128 + nbase;
        *(float4*)cp            = make_float4(u0.x, u1.x, u2.x, u3.x);
        *(float4*)(cp + ldc)    = make_float4(u0.y, u1.y, u2.y, u3.y);
    }
}

// ---------------- weight concat [Wk | Wv] ----------------
__global__ void concat_wkv(const float* __restrict__ Wk, const float* __restrict__ Wv,
                           float* __restrict__ Wkv) {
    int idx = blockIdx.x * 256 + threadIdx.x;      // HID*512
    int k = idx >> 9, n = idx & 511;
    Wkv[idx] = (n < 256) ? Wk[k * 256 + n] : Wv[k * 256 + (n - 256)];
}

// ---------------- RoPE Q: block per token ----------------
__global__ __launch_bounds__(256)
void rope_q(const float* __restrict__ Qp, const float* __restrict__ cosb,
            const float* __restrict__ sinb, float* __restrict__ Qt) {
    const int bs = blockIdx.x;            // 0..4095
    const int b = bs >> 11, s = bs & 2047;
    const int d = threadIdx.x;            // 0..255
    const int dp = (d < 128) ? d + 128 : d - 128;
    const float cd = cosb[(long)bs * 256 + d];
    const float sd = sinb[(long)bs * 256 + d];
    const float sgn = (d < 128) ? -1.0f : 1.0f;

    const float* src = Qp + (long)bs * 2048;
    float x[8], xp[8];
    #pragma unroll
    for (int h = 0; h < 8; h++) x[h]  = src[h * 256 + d];
    #pragma unroll
    for (int h = 0; h < 8; h++) xp[h] = src[h * 256 + dp];
    #pragma unroll
    for (int h = 0; h < 8; h++) {
        Qt[(((long)(b * 8 + h) * 2048 + s) << 8) + d] =
            (x[h] * cd + sgn * xp[h] * sd) * SCALING;
    }
}

// ---------------- RoPE K + transpose -> Kt (b, d, s2) ----------------
__global__ void rope_kT(const float* __restrict__ KV, const float* __restrict__ cosb,
                        const float* __restrict__ sinb, float* __restrict__ Kt) {
    __shared__ float t[32][33];
    const int b = blockIdx.z;
    const int d0 = blockIdx.y * 32;
    const int s0 = blockIdx.x * 32;
    const int tx = threadIdx.x, ty = threadIdx.y;

    const int d = d0 + tx;
    const int s2 = s0 + ty;
    const int dp = (d < 128) ? d + 128 : d - 128;
    const long tok = (long)(b * SEQ + s2);
    const float x  = KV[tok * 512 + d];
    const float xp = KV[tok * 512 + dp];
    const float rot = (d < 128) ? -xp : xp;
    const float c = cosb[tok * 256 + d];
    const float sv = sinb[tok * 256 + d];
    t[ty][tx] = x * c + rot * sv;
    __syncthreads();

    Kt[((long)(b * HD + d0 + ty)) * SEQ + s0 + tx] = t[tx][ty];
}

// ---------------- causal softmax ----------------
__global__ __launch_bounds__(256)
void softmax_causal(float* __restrict__ W) {
    const long row = blockIdx.x;                 // (b,h,s1) flat
    const int r = (int)(row & 2047);
    const int len = r + 1;
    float* p = W + row * (long)SEQ;
    const int tid = threadIdx.x;
    __shared__ float red[256];

    float v[8];
    float m = -3.0e38f;
    #pragma unroll
    for (int j = 0; j < 8; j++) {
        const int c = tid + j * 256;
        v[j] = (c < len) ? p[c] : -3.0e38f;
        m = fmaxf(m, v[j]);
    }
    red[tid] = m; __syncthreads();
    for (int s = 128; s > 0; s >>= 1) {
        if (tid < s) red[tid] = fmaxf(red[tid], red[tid + s]);
        __syncthreads();
    }
    m = red[0]; __syncthreads();

    float sum = 0.0f;
    #pragma unroll
    for (int j = 0; j < 8; j++) {
        const int c = tid + j * 256;
        v[j] = (c < len) ? __expf(v[j] - m) : 0.0f;
        sum += v[j];
    }
    red[tid] = sum; __syncthreads();
    for (int s = 128; s > 0; s >>= 1) {
        if (tid < s) red[tid] += red[tid + s];
        __syncthreads();
    }
    const float inv = 1.0f / red[0]; __syncthreads();

    #pragma unroll
    for (int j = 0; j < 8; j++) {
        const int c = tid + j * 256;
        p[c] = v[j] * inv;          // exact 0 above diagonal
    }
}

// ---------------- launch ----------------
extern "C" void kernel_launch(void* const* d_in, const int* in_sizes, int n_in,
                              void* d_out, int out_size)
{
    const float* hs   = (const float*)d_in[0];
    const float* cosb = (const float*)d_in[1];
    const float* sinb = (const float*)d_in[2];
    const float* Wq   = (const float*)d_in[4];
    const float* Wk   = (const float*)d_in[5];
    const float* Wv   = (const float*)d_in[6];
    const float* Wo   = (const float*)d_in[7];

    float* out_attn = (float*)d_out;                          // (B,S,H)
    float* out_w    = (float*)d_out + (long)BSZ * SEQ * HID;  // (B,NH,S,S)

    const long SS = (long)SEQ * SEQ;

    // 0) concat K/V weights
    concat_wkv<<<(HID * 512) / 256, 256>>>(Wk, Wv, g_Wkv);

    // 1) Q projection
    sgemm3<<<dim3(16, 32, 1), 512>>>(hs, Wq, g_Qp,
        HID, HID, HID, HID, 0, 0, 0, 0, 1, 0, 0);

    // 2) KV projection
    sgemm3<<<dim3(4, 32, 1), 512>>>(hs, g_Wkv, g_KV,
        HID, HID, 512, 512, 0, 0, 0, 0, 1, 0, 0);

    // 3) RoPE
    rope_q <<<4096, 256>>>(g_Qp, cosb, sinb, g_Q);
    rope_kT<<<dim3(64, 8, 2), dim3(32, 32)>>>(g_KV, cosb, sinb, g_Kt);

    // 4) logits = Q K^T (scaled via Q), causal tile skip
    sgemm3<<<dim3(16, 16, 16), 512>>>(g_Q, g_Kt, out_w,
        HD, HD, SEQ, SEQ,
        (long)SEQ * HD, (long)HD * SEQ, (long)NH * SS, SS, NH, 1, 0);

    // 5) causal softmax
    softmax_causal<<<32768, 256>>>(out_w);

    // 6) attn = P @ V, K-loop truncated by causality
    sgemm3<<<dim3(2, 16, 16), 512>>>(out_w, g_KV + 256, g_AO,
        SEQ, SEQ, 512, HID,
        SS, (long)SEQ * 512, (long)SEQ * HID, (long)HD, NH, 0, 1);

    // 7) output projection
    sgemm3<<<dim3(16, 32, 1), 512>>>(g_AO, Wo, out_attn,
        HID, HID, HID, HID, 0, 0, 0, 0, 1, 0, 0);
}